// round 3
// baseline (speedup 1.0000x reference)
#include <cuda_runtime.h>
#include <cstdint>

#define N_NODES 200000
#define E_CAP   3200000
#define D 64

// ---------------------------------------------------------------------------
// Scratch (allocation-free rule: __device__ globals)
// ---------------------------------------------------------------------------
__device__ float g_nbr[(size_t)N_NODES * D];      // 51.2 MB
__device__ float g_h1 [(size_t)N_NODES * D];      // 51.2 MB
__device__ int   g_cnt   [N_NODES];               // per-row edge counts
__device__ int   g_rowptr[N_NODES + 1];           // CSR row pointers
__device__ int   g_cursor[N_NODES];               // scatter cursors
__device__ int2  g_cv    [E_CAP];                 // packed (col, val-bits), 25.6 MB

// ---------------------------------------------------------------------------
// CSR build step 1: zero counts
// ---------------------------------------------------------------------------
__global__ void zero_int_kernel(int* __restrict__ p, int n) {
    int i = blockIdx.x * blockDim.x + threadIdx.x;
    int stride = gridDim.x * blockDim.x;
    for (; i < n; i += stride) p[i] = 0;
}

// CSR build step 2: histogram of destination rows
__global__ void hist_kernel(const int* __restrict__ rows, int* __restrict__ cnt, int E) {
    int i = blockIdx.x * blockDim.x + threadIdx.x;
    int stride = gridDim.x * blockDim.x;
    for (; i < E; i += stride) atomicAdd(&cnt[__ldg(rows + i)], 1);
}

// CSR build step 3: single-block exclusive scan -> rowptr, cursor
__global__ void __launch_bounds__(1024)
scan_kernel(const int* __restrict__ cnt, int* __restrict__ rowptr,
            int* __restrict__ cursor, int n) {
    __shared__ int psum[1024];
    int tid = threadIdx.x;
    int per = (n + 1023) >> 10;
    int start = tid * per;
    int end   = start + per; if (end > n) end = n;
    if (start > n) start = n;

    int s = 0;
    for (int i = start; i < end; i++) s += cnt[i];
    psum[tid] = s;
    __syncthreads();

    // inclusive Hillis-Steele scan over 1024 partials
    for (int off = 1; off < 1024; off <<= 1) {
        int t = (tid >= off) ? psum[tid - off] : 0;
        __syncthreads();
        psum[tid] += t;
        __syncthreads();
    }

    int run = psum[tid] - s;   // exclusive prefix for this thread's chunk
    for (int i = start; i < end; i++) {
        rowptr[i] = run;
        cursor[i] = run;
        run += cnt[i];
    }
    if (tid == 1023) rowptr[n] = psum[1023];
}

// CSR build step 4: scatter edges into row-grouped (col,val) pairs
__global__ void scatter_kernel(const int*   __restrict__ rows,
                               const int*   __restrict__ cols,
                               const float* __restrict__ vals,
                               int*  __restrict__ cursor,
                               int2* __restrict__ cv, int E) {
    int i = blockIdx.x * blockDim.x + threadIdx.x;
    int stride = gridDim.x * blockDim.x;
    for (; i < E; i += stride) {
        int r   = __ldg(rows + i);
        int pos = atomicAdd(&cursor[r], 1);
        cv[pos] = make_int2(__ldg(cols + i), __float_as_int(__ldg(vals + i)));
    }
}

// ---------------------------------------------------------------------------
// Pull-mode SpMM: out[n] = sum_{e in row n} val[e] * x[col[e]]
// One warp per node; lane owns float2 chunk `lane` of the 64-float row.
// Per edge: one broadcast LDG.64 of (col,val) + one coalesced 256B gather.
// Accumulate in registers, single clean 256B store per node. No atomics.
// ---------------------------------------------------------------------------
__global__ void __launch_bounds__(256)
spmm_pull_kernel(const int*  __restrict__ rowptr,
                 const int2* __restrict__ cv,
                 const float* __restrict__ x,
                 float*       __restrict__ out,
                 int N) {
    int warp = (blockIdx.x * blockDim.x + threadIdx.x) >> 5;
    if (warp >= N) return;
    int lane = threadIdx.x & 31;

    int s = __ldg(rowptr + warp);
    int e = __ldg(rowptr + warp + 1);

    const float2* x2 = (const float2*)x;
    float2 acc = make_float2(0.f, 0.f);

    int i = s;
    for (; i + 1 < e; i += 2) {
        int2 c0 = __ldg(cv + i);
        int2 c1 = __ldg(cv + i + 1);
        float2 a = __ldg(x2 + (long long)c0.x * 32 + lane);
        float2 b = __ldg(x2 + (long long)c1.x * 32 + lane);
        float v0 = __int_as_float(c0.y);
        float v1 = __int_as_float(c1.y);
        acc.x += v0 * a.x;  acc.y += v0 * a.y;
        acc.x += v1 * b.x;  acc.y += v1 * b.y;
    }
    if (i < e) {
        int2 c0 = __ldg(cv + i);
        float2 a = __ldg(x2 + (long long)c0.x * 32 + lane);
        float v0 = __int_as_float(c0.y);
        acc.x += v0 * a.x;  acc.y += v0 * a.y;
    }

    ((float2*)out)[(long long)warp * 32 + lane] = acc;
}

// ---------------------------------------------------------------------------
// Fused concat + GEMM + bias + ReLU (unchanged from R2; W staged in smem,
// X rows staged with pitch-65 padding; 2 rows x 16 cols per thread).
// ---------------------------------------------------------------------------
#define DB_ROWS 128
#define DB_THREADS 256
#define XPITCH 65
#define DENSE_SMEM ((128*64 + 2*DB_ROWS*XPITCH) * sizeof(float))

__global__ void __launch_bounds__(DB_THREADS)
dense_kernel(const float* __restrict__ Xh,
             const float* __restrict__ Xn,
             const float* __restrict__ W,   // [128][64] row-major
             const float* __restrict__ b,   // [64]
             float*       __restrict__ out, // [N][64]
             int N) {
    extern __shared__ float sm[];
    float*  Ws  = sm;                 // 128*64 floats
    float*  Xs  = sm + 128 * 64;      // [2][DB_ROWS][XPITCH]
    float4* Ws4 = (float4*)Ws;

    int tid  = threadIdx.x;
    int base = blockIdx.x * DB_ROWS;

    const float4* Wg = (const float4*)W;
    for (int i = tid; i < 128 * 16; i += DB_THREADS) Ws4[i] = __ldg(Wg + i);

    int nr = N - base; if (nr > DB_ROWS) nr = DB_ROWS;
    for (int i = tid; i < nr * D; i += DB_THREADS) {
        int r = i >> 6, c = i & 63;
        Xs[r * XPITCH + c]                    = __ldg(Xh + (size_t)(base + r) * D + c);
        Xs[DB_ROWS * XPITCH + r * XPITCH + c] = __ldg(Xn + (size_t)(base + r) * D + c);
    }
    __syncthreads();

    int q    = tid & 3;
    int slot = tid >> 2;

    float4 a0[4], a1[4];
    #pragma unroll
    for (int v = 0; v < 4; v++) {
        float4 bv = __ldg(((const float4*)b) + q * 4 + v);
        a0[v] = bv; a1[v] = bv;
    }

    const float* xh0 = Xs + slot * XPITCH;
    const float* xh1 = Xs + (slot + 64) * XPITCH;
    const float* xn0 = Xs + DB_ROWS * XPITCH + slot * XPITCH;
    const float* xn1 = Xs + DB_ROWS * XPITCH + (slot + 64) * XPITCH;

    #pragma unroll 4
    for (int k = 0; k < 64; k++) {
        float h0 = xh0[k], h1 = xh1[k];
        float n0 = xn0[k], n1 = xn1[k];
        #pragma unroll
        for (int v = 0; v < 4; v++) {
            float4 wh = Ws4[k * 16 + q * 4 + v];
            float4 wn = Ws4[(64 + k) * 16 + q * 4 + v];
            a0[v].x += h0 * wh.x + n0 * wn.x;
            a0[v].y += h0 * wh.y + n0 * wn.y;
            a0[v].z += h0 * wh.z + n0 * wn.z;
            a0[v].w += h0 * wh.w + n0 * wn.w;
            a1[v].x += h1 * wh.x + n1 * wn.x;
            a1[v].y += h1 * wh.y + n1 * wn.y;
            a1[v].z += h1 * wh.z + n1 * wn.z;
            a1[v].w += h1 * wh.w + n1 * wn.w;
        }
    }

    float4* out4 = (float4*)out;
    int r0 = base + slot, r1 = base + slot + 64;
    if (r0 < N) {
        #pragma unroll
        for (int v = 0; v < 4; v++) {
            float4 t = a0[v];
            t.x = fmaxf(t.x, 0.f); t.y = fmaxf(t.y, 0.f);
            t.z = fmaxf(t.z, 0.f); t.w = fmaxf(t.w, 0.f);
            out4[(size_t)r0 * 16 + q * 4 + v] = t;
        }
    }
    if (r1 < N) {
        #pragma unroll
        for (int v = 0; v < 4; v++) {
            float4 t = a1[v];
            t.x = fmaxf(t.x, 0.f); t.y = fmaxf(t.y, 0.f);
            t.z = fmaxf(t.z, 0.f); t.w = fmaxf(t.w, 0.f);
            out4[(size_t)r1 * 16 + q * 4 + v] = t;
        }
    }
}

// ---------------------------------------------------------------------------
extern "C" void kernel_launch(void* const* d_in, const int* in_sizes, int n_in,
                              void* d_out, int out_size) {
    const int*   rows = (const int*)  d_in[0];
    const int*   cols = (const int*)  d_in[1];
    const float* vals = (const float*)d_in[2];
    const float* emb  = (const float*)d_in[3];
    const float* W1   = (const float*)d_in[4];
    const float* b1   = (const float*)d_in[5];
    const float* W2   = (const float*)d_in[6];
    const float* b2   = (const float*)d_in[7];
    float* out = (float*)d_out;

    int E = in_sizes[0];
    int N = in_sizes[3] / D;

    float *nbr, *h1;
    int *cnt, *rowptr, *cursor;
    int2 *cv;
    cudaGetSymbolAddress((void**)&nbr,    g_nbr);
    cudaGetSymbolAddress((void**)&h1,     g_h1);
    cudaGetSymbolAddress((void**)&cnt,    g_cnt);
    cudaGetSymbolAddress((void**)&rowptr, g_rowptr);
    cudaGetSymbolAddress((void**)&cursor, g_cursor);
    cudaGetSymbolAddress((void**)&cv,     g_cv);

    cudaFuncSetAttribute(dense_kernel,
                         cudaFuncAttributeMaxDynamicSharedMemorySize,
                         (int)DENSE_SMEM);

    int eb = (E + 255) / 256;
    int dense_blocks = (N + DB_ROWS - 1) / DB_ROWS;
    int pull_blocks  = (N * 32 + 255) / 256;   // warp per node

    // ---- CSR build (amortized over both layers) ----
    zero_int_kernel<<<(N + 255) / 256, 256>>>(cnt, N);
    hist_kernel   <<<eb, 256>>>(rows, cnt, E);
    scan_kernel   <<<1, 1024>>>(cnt, rowptr, cursor, N);
    scatter_kernel<<<eb, 256>>>(rows, cols, vals, cursor, cv, E);

    // ---- Layer 1 ----
    spmm_pull_kernel<<<pull_blocks, 256>>>(rowptr, cv, emb, nbr, N);
    dense_kernel<<<dense_blocks, DB_THREADS, DENSE_SMEM>>>(emb, nbr, W1, b1, h1, N);

    // ---- Layer 2 ----
    spmm_pull_kernel<<<pull_blocks, 256>>>(rowptr, cv, h1, nbr, N);
    dense_kernel<<<dense_blocks, DB_THREADS, DENSE_SMEM>>>(h1, nbr, W2, b2, out, N);
}

// round 4
// speedup vs baseline: 1.0989x; 1.0989x over previous
#include <cuda_runtime.h>
#include <cstdint>

#define N_NODES 200000
#define E_CAP   3200000
#define D 64

typedef unsigned long long u64;

// ---------------------------------------------------------------------------
// Scratch (allocation-free rule: __device__ globals)
// ---------------------------------------------------------------------------
__device__ float g_nbr[(size_t)N_NODES * D];      // 51.2 MB
__device__ float g_h1 [(size_t)N_NODES * D];      // 51.2 MB
__device__ int   g_cnt   [N_NODES];
__device__ int   g_rowptr[N_NODES + 1];
__device__ int   g_cursor[N_NODES];
__device__ int2  g_cv    [E_CAP];                 // packed (col, val-bits)

// ---------------------------------------------------------------------------
// Packed fp32x2 helpers (Blackwell fma.rn.f32x2: 2 fp32 FMAs / instruction)
// ---------------------------------------------------------------------------
__device__ __forceinline__ void fma2(u64& d, u64 a, u64 b) {
    asm("fma.rn.f32x2 %0, %1, %2, %0;" : "+l"(d) : "l"(a), "l"(b));
}
__device__ __forceinline__ u64 pk2(float lo, float hi) {
    u64 r; asm("mov.b64 %0, {%1, %2};" : "=l"(r) : "f"(lo), "f"(hi)); return r;
}
__device__ __forceinline__ u64 dup2(float x) {
    u64 r; asm("mov.b64 %0, {%1, %1};" : "=l"(r) : "f"(x)); return r;
}
__device__ __forceinline__ float2 upk2(u64 v) {
    float2 f; asm("mov.b64 {%0, %1}, %2;" : "=f"(f.x), "=f"(f.y) : "l"(v)); return f;
}

// ---------------------------------------------------------------------------
// CSR build
// ---------------------------------------------------------------------------
__global__ void zero_int_kernel(int* __restrict__ p, int n) {
    int i = blockIdx.x * blockDim.x + threadIdx.x;
    int stride = gridDim.x * blockDim.x;
    for (; i < n; i += stride) p[i] = 0;
}

__global__ void hist_kernel(const int* __restrict__ rows, int* __restrict__ cnt, int E) {
    int i = blockIdx.x * blockDim.x + threadIdx.x;
    int stride = gridDim.x * blockDim.x;
    for (; i < E; i += stride) atomicAdd(&cnt[__ldg(rows + i)], 1);
}

__global__ void __launch_bounds__(1024)
scan_kernel(const int* __restrict__ cnt, int* __restrict__ rowptr,
            int* __restrict__ cursor, int n) {
    __shared__ int psum[1024];
    int tid = threadIdx.x;
    int per = (n + 1023) >> 10;
    int start = tid * per;
    int end   = start + per; if (end > n) end = n;
    if (start > n) start = n;

    int s = 0;
    for (int i = start; i < end; i++) s += cnt[i];
    psum[tid] = s;
    __syncthreads();
    for (int off = 1; off < 1024; off <<= 1) {
        int t = (tid >= off) ? psum[tid - off] : 0;
        __syncthreads();
        psum[tid] += t;
        __syncthreads();
    }
    int run = psum[tid] - s;
    for (int i = start; i < end; i++) {
        rowptr[i] = run;
        cursor[i] = run;
        run += cnt[i];
    }
    if (tid == 1023) rowptr[n] = psum[1023];
}

__global__ void scatter_kernel(const int*   __restrict__ rows,
                               const int*   __restrict__ cols,
                               const float* __restrict__ vals,
                               int*  __restrict__ cursor,
                               int2* __restrict__ cv, int E) {
    int i = blockIdx.x * blockDim.x + threadIdx.x;
    int stride = gridDim.x * blockDim.x;
    for (; i < E; i += stride) {
        int r   = __ldg(rows + i);
        int pos = atomicAdd(&cursor[r], 1);
        cv[pos] = make_int2(__ldg(cols + i), __float_as_int(__ldg(vals + i)));
    }
}

// ---------------------------------------------------------------------------
// Pull-mode SpMM, high-MLP variant.
// Warp per node; lane owns float2 chunk of the 64-float row.
// Metadata for up to 32 edges fetched in ONE coalesced LDG.64 (lane i -> edge
// base+i), then broadcast via shfl. Gathers are issued as 2 independent
// chains -> >=2 loads in flight per warp (no cv->gather dependency).
// Single clean 256B store per node. No atomics.
// ---------------------------------------------------------------------------
__global__ void __launch_bounds__(512)
spmm_pull_kernel(const int*  __restrict__ rowptr,
                 const int2* __restrict__ cv,
                 const float* __restrict__ x,
                 float*       __restrict__ out,
                 int N) {
    int warp = (blockIdx.x * blockDim.x + threadIdx.x) >> 5;
    if (warp >= N) return;
    int lane = threadIdx.x & 31;

    int s = __ldg(rowptr + warp);
    int e = __ldg(rowptr + warp + 1);

    const float2* x2 = (const float2*)x;
    float2 acc0 = make_float2(0.f, 0.f);
    float2 acc1 = make_float2(0.f, 0.f);

    for (int base = s; base < e; base += 32) {
        int idx = base + lane;
        int2 c = (idx < e) ? __ldg(cv + idx) : make_int2(0, 0);
        int m = e - base; if (m > 32) m = 32;

        int j = 0;
        for (; j + 1 < m; j += 2) {
            int col0 = __shfl_sync(0xFFFFFFFFu, c.x, j);
            int vb0  = __shfl_sync(0xFFFFFFFFu, c.y, j);
            int col1 = __shfl_sync(0xFFFFFFFFu, c.x, j + 1);
            int vb1  = __shfl_sync(0xFFFFFFFFu, c.y, j + 1);
            float2 g0 = __ldg(x2 + (long long)col0 * 32 + lane);
            float2 g1 = __ldg(x2 + (long long)col1 * 32 + lane);
            float v0 = __int_as_float(vb0);
            float v1 = __int_as_float(vb1);
            acc0.x += v0 * g0.x;  acc0.y += v0 * g0.y;
            acc1.x += v1 * g1.x;  acc1.y += v1 * g1.y;
        }
        if (j < m) {
            int col0 = __shfl_sync(0xFFFFFFFFu, c.x, j);
            float v0 = __int_as_float(__shfl_sync(0xFFFFFFFFu, c.y, j));
            float2 g0 = __ldg(x2 + (long long)col0 * 32 + lane);
            acc0.x += v0 * g0.x;  acc0.y += v0 * g0.y;
        }
    }

    float2 r = make_float2(acc0.x + acc1.x, acc0.y + acc1.y);
    ((float2*)out)[(long long)warp * 32 + lane] = r;
}

// ---------------------------------------------------------------------------
// Fused concat + GEMM + bias + ReLU with packed f32x2 FMAs.
// Block: 256 threads, 128 rows. W (128x64) in smem; X rows staged pitch-65.
// Thread: 2 rows x 16 cols = 16 u64 accumulators; per k: 8 LDS.128 (W) +
// 4 scalar LDS (X) + 32 fma.rn.f32x2.
// ---------------------------------------------------------------------------
#define DB_ROWS 128
#define DB_THREADS 256
#define XPITCH 65
#define DENSE_SMEM ((128*64 + 2*DB_ROWS*XPITCH) * sizeof(float))

__global__ void __launch_bounds__(DB_THREADS)
dense_kernel(const float* __restrict__ Xh,
             const float* __restrict__ Xn,
             const float* __restrict__ W,   // [128][64] row-major
             const float* __restrict__ b,   // [64]
             float*       __restrict__ out, // [N][64]
             int N) {
    extern __shared__ float sm[];
    float*  Ws  = sm;                 // 128*64 floats
    float*  Xs  = sm + 128 * 64;      // [2][DB_ROWS][XPITCH]
    float4* Ws4 = (float4*)Ws;

    int tid  = threadIdx.x;
    int base = blockIdx.x * DB_ROWS;

    const float4* Wg = (const float4*)W;
    for (int i = tid; i < 128 * 16; i += DB_THREADS) Ws4[i] = __ldg(Wg + i);

    int nr = N - base; if (nr > DB_ROWS) nr = DB_ROWS;
    for (int i = tid; i < nr * D; i += DB_THREADS) {
        int r = i >> 6, c = i & 63;
        Xs[r * XPITCH + c]                    = __ldg(Xh + (size_t)(base + r) * D + c);
        Xs[DB_ROWS * XPITCH + r * XPITCH + c] = __ldg(Xn + (size_t)(base + r) * D + c);
    }
    __syncthreads();

    int q    = tid & 3;     // column quarter: j in [16q, 16q+16)
    int slot = tid >> 2;    // rows slot and slot+64

    // 16 packed accumulators per row-group (2 cols each)
    u64 a0[8], a1[8];
    #pragma unroll
    for (int v = 0; v < 4; v++) {
        float4 bv = __ldg(((const float4*)b) + q * 4 + v);
        a0[2*v]   = pk2(bv.x, bv.y);
        a0[2*v+1] = pk2(bv.z, bv.w);
        a1[2*v]   = a0[2*v];
        a1[2*v+1] = a0[2*v+1];
    }

    const float* xh0 = Xs + slot * XPITCH;
    const float* xh1 = Xs + (slot + 64) * XPITCH;
    const float* xn0 = Xs + DB_ROWS * XPITCH + slot * XPITCH;
    const float* xn1 = Xs + DB_ROWS * XPITCH + (slot + 64) * XPITCH;

    const ulonglong2* Wsp = (const ulonglong2*)Ws;   // float4 <-> ulonglong2

    #pragma unroll 4
    for (int k = 0; k < 64; k++) {
        u64 h0 = dup2(xh0[k]);
        u64 h1 = dup2(xh1[k]);
        u64 n0 = dup2(xn0[k]);
        u64 n1 = dup2(xn1[k]);
        #pragma unroll
        for (int v = 0; v < 4; v++) {
            ulonglong2 wh = Wsp[k * 16 + q * 4 + v];
            ulonglong2 wn = Wsp[(64 + k) * 16 + q * 4 + v];
            fma2(a0[2*v],   h0, wh.x);  fma2(a0[2*v+1], h0, wh.y);
            fma2(a0[2*v],   n0, wn.x);  fma2(a0[2*v+1], n0, wn.y);
            fma2(a1[2*v],   h1, wh.x);  fma2(a1[2*v+1], h1, wh.y);
            fma2(a1[2*v],   n1, wn.x);  fma2(a1[2*v+1], n1, wn.y);
        }
    }

    float4* out4 = (float4*)out;
    int r0 = base + slot, r1 = base + slot + 64;
    if (r0 < N) {
        #pragma unroll
        for (int v = 0; v < 4; v++) {
            float2 lo = upk2(a0[2*v]), hi = upk2(a0[2*v+1]);
            float4 t;
            t.x = fmaxf(lo.x, 0.f); t.y = fmaxf(lo.y, 0.f);
            t.z = fmaxf(hi.x, 0.f); t.w = fmaxf(hi.y, 0.f);
            out4[(size_t)r0 * 16 + q * 4 + v] = t;
        }
    }
    if (r1 < N) {
        #pragma unroll
        for (int v = 0; v < 4; v++) {
            float2 lo = upk2(a1[2*v]), hi = upk2(a1[2*v+1]);
            float4 t;
            t.x = fmaxf(lo.x, 0.f); t.y = fmaxf(lo.y, 0.f);
            t.z = fmaxf(hi.x, 0.f); t.w = fmaxf(hi.y, 0.f);
            out4[(size_t)r1 * 16 + q * 4 + v] = t;
        }
    }
}

// ---------------------------------------------------------------------------
extern "C" void kernel_launch(void* const* d_in, const int* in_sizes, int n_in,
                              void* d_out, int out_size) {
    const int*   rows = (const int*)  d_in[0];
    const int*   cols = (const int*)  d_in[1];
    const float* vals = (const float*)d_in[2];
    const float* emb  = (const float*)d_in[3];
    const float* W1   = (const float*)d_in[4];
    const float* b1   = (const float*)d_in[5];
    const float* W2   = (const float*)d_in[6];
    const float* b2   = (const float*)d_in[7];
    float* out = (float*)d_out;

    int E = in_sizes[0];
    int N = in_sizes[3] / D;

    float *nbr, *h1;
    int *cnt, *rowptr, *cursor;
    int2 *cv;
    cudaGetSymbolAddress((void**)&nbr,    g_nbr);
    cudaGetSymbolAddress((void**)&h1,     g_h1);
    cudaGetSymbolAddress((void**)&cnt,    g_cnt);
    cudaGetSymbolAddress((void**)&rowptr, g_rowptr);
    cudaGetSymbolAddress((void**)&cursor, g_cursor);
    cudaGetSymbolAddress((void**)&cv,     g_cv);

    cudaFuncSetAttribute(dense_kernel,
                         cudaFuncAttributeMaxDynamicSharedMemorySize,
                         (int)DENSE_SMEM);

    int eb = (E + 255) / 256;
    int dense_blocks = (N + DB_ROWS - 1) / DB_ROWS;
    int pull_blocks  = (N * 32 + 511) / 512;   // warp per node

    // ---- CSR build (amortized over both layers) ----
    zero_int_kernel<<<(N + 255) / 256, 256>>>(cnt, N);
    hist_kernel   <<<eb, 256>>>(rows, cnt, E);
    scan_kernel   <<<1, 1024>>>(cnt, rowptr, cursor, N);
    scatter_kernel<<<eb, 256>>>(rows, cols, vals, cursor, cv, E);

    // ---- Layer 1 ----
    spmm_pull_kernel<<<pull_blocks, 512>>>(rowptr, cv, emb, nbr, N);
    dense_kernel<<<dense_blocks, DB_THREADS, DENSE_SMEM>>>(emb, nbr, W1, b1, h1, N);

    // ---- Layer 2 ----
    spmm_pull_kernel<<<pull_blocks, 512>>>(rowptr, cv, h1, nbr, N);
    dense_kernel<<<dense_blocks, DB_THREADS, DENSE_SMEM>>>(h1, nbr, W2, b2, out, N);
}